// round 14
// baseline (speedup 1.0000x reference)
#include <cuda_runtime.h>
#include <cuda_bf16.h>
#include <math.h>

// Problem constants
#define SEQ_LEN   512
#define PRED_LEN  96
#define PATCH_LEN 16
#define STRIDE    8
#define NQ        4
#define NLAYERS   3
#define NPATCH    63           // (512-16)/8+1
#define BATCH     32
#define CHANS     128
#define NCH       (BATCH*CHANS)        // 4096
#define FAN_IN    (NPATCH*NQ)          // 252
#define FPAD      256                  // head k padded to 256
#define NPAIR     136                  // 16*17/2
#define SKIP_BLOCKS (12*32)            // 384, placed FIRST in the fused grid
#define ENC_BLOCKS  1008               // (63*4096/2)/128

typedef unsigned long long ull;

// ---- packed f32x2 helpers (sm_103a) ---------------------------------------
__device__ __forceinline__ ull fma2(ull a, ull b, ull c) {
    ull d; asm("fma.rn.f32x2 %0, %1, %2, %3;" : "=l"(d) : "l"(a), "l"(b), "l"(c)); return d;
}
__device__ __forceinline__ ull mul2(ull a, ull b) {
    ull d; asm("mul.rn.f32x2 %0, %1, %2;" : "=l"(d) : "l"(a), "l"(b)); return d;
}
__device__ __forceinline__ ull add2(ull a, ull b) {
    ull d; asm("add.rn.f32x2 %0, %1, %2;" : "=l"(d) : "l"(a), "l"(b)); return d;
}
__device__ __forceinline__ ull pack2(float lo, float hi) {
    ull d; asm("mov.b64 %0, {%1, %2};" : "=l"(d) : "f"(lo), "f"(hi)); return d;
}
__device__ __forceinline__ float lo2(ull a) { return __uint_as_float((unsigned)(a & 0xffffffffull)); }
__device__ __forceinline__ float hi2(ull a) { return __uint_as_float((unsigned)(a >> 32)); }

// Scratch (device globals; no allocation allowed)
__device__ float d_encT[FPAD * NCH];    // enc transposed [f][n]; rows 252..255 zero (4MB)

// ---------------------------------------------------------------------------
// GEMM segment: LDG.128 data (4 adjacent channels per load), dup-packed
// weights via broadcast LDS.128. Per chunk (4 k): 4 LDG.128 + 16 LDS.128 +
// 64 FFMA2 => 128 MACs. STRIDE_U2 = row stride in ulonglong2 (compile-time).
// ---------------------------------------------------------------------------
template<int STRIDE_U2>
__device__ __forceinline__ void gemm_seg(const ulonglong2* __restrict__ p, int nchunks,
                                         const ulonglong2* __restrict__ sw,
                                         ull acc[2][8]) {
    #pragma unroll 1
    for (int c = 0; c < nchunks; c++) {
        ulonglong2 V[4];
        #pragma unroll
        for (int i = 0; i < 4; i++)
            V[i] = __ldg(p + i * STRIDE_U2);
        #pragma unroll
        for (int i = 0; i < 4; i++) {
            ull v0 = V[i].x, v1 = V[i].y;
            #pragma unroll
            for (int j = 0; j < 4; j++) {
                ulonglong2 q = sw[i*4 + j];
                acc[0][2*j]   = fma2(v0, q.x, acc[0][2*j]);
                acc[0][2*j+1] = fma2(v0, q.y, acc[0][2*j+1]);
                acc[1][2*j]   = fma2(v1, q.x, acc[1][2*j]);
                acc[1][2*j+1] = fma2(v1, q.y, acc[1][2*j+1]);
            }
        }
        p  += 4 * STRIDE_U2;
        sw += 16;
    }
}

// ---------------------------------------------------------------------------
// Kernel A: heterogeneous fused launch (128-thread blocks). UNCHANGED r13.
//   blocks [0, 384):    skip-GEMM, full 512 k; writes out = skip + biases.
//   blocks [384, 1392): encoder.
// ---------------------------------------------------------------------------
__global__ __launch_bounds__(128, 8) void fused_enc_skip(
    const float* __restrict__ x,
    const float* __restrict__ weights,
    const float* __restrict__ skip_w,
    const float* __restrict__ head_b,
    const float* __restrict__ skip_b,
    float* __restrict__ out)
{
    __shared__ float2 sG[12][4];
    __shared__ float2 sU[16][16];
    __shared__ ulonglong2 sM[NPAIR * 2];
    __shared__ ull sS[64 * 33];            // 16.5KB: stage (2048/pass) / reduce (2112)

    int tid = threadIdx.x;                 // 0..127

    if (blockIdx.x < SKIP_BLOCKS) {
        // =================== SKIP-GEMM (full k) ===================
        int ot = blockIdx.x % 12;
        int b  = blockIdx.x / 12;
        int o0 = ot * 8;

        int cpg = tid & 31;                // 4 channels: 4cpg..4cpg+3
        int g   = tid >> 5;                // 0..3

        ull acc[2][8];
        #pragma unroll
        for (int s = 0; s < 2; s++)
            #pragma unroll
            for (int r = 0; r < 8; r++) acc[s][r] = 0ULL;

        #pragma unroll 1
        for (int pass = 0; pass < 2; pass++) {
            #pragma unroll
            for (int it = 0; it < 16; it++) {
                int idx = it * 128 + tid;  // < 2048
                int r  = idx >> 8;
                int kk = idx & 255;
                float w = skip_w[(o0 + r) * SEQ_LEN + pass * 256 + kk];
                sS[kk * 8 + r] = pack2(w, w);
            }
            __syncthreads();

            const ulonglong2* xp = (const ulonglong2*)x
                + ((size_t)b * SEQ_LEN + pass * 256 + g * 64) * (CHANS/4) + cpg;
            gemm_seg<CHANS/4>(xp, 16, (const ulonglong2*)sS + (g * 64) * 4, acc);
            __syncthreads();
        }

        #pragma unroll
        for (int s = 0; s < 2; s++) {
            int cp = 2 * cpg + s;
            #pragma unroll
            for (int r = 0; r < 8; r++)
                sS[cp * 33 + g * 8 + r] = acc[s][r];
        }
        __syncthreads();

        int cp = tid & 63;
        int q  = tid >> 6;                 // 0..1
        #pragma unroll
        for (int t = 0; t < 4; t++) {
            int oo = 4 * q + t;
            ull s = add2(add2(sS[cp*33 + 0*8 + oo], sS[cp*33 + 1*8 + oo]),
                         add2(sS[cp*33 + 2*8 + oo], sS[cp*33 + 3*8 + oo]));
            float bias = head_b[o0 + oo] + skip_b[o0 + oo];
            s = add2(s, pack2(bias, bias));
            ((ull*)out)[((size_t)b * PRED_LEN + o0 + oo) * (CHANS/2) + cp] = s;
        }
        return;
    }

    // ======================= ENCODER =======================
    int gtid = (blockIdx.x - SKIP_BLOCKS) * 128 + tid;   // < 129024

    if (gtid < 8192)
        ((ull*)(d_encT + (size_t)FAN_IN * NCH))[gtid] = 0ULL;

    if (tid < 12) {
        float phi   = weights[tid*3 + 0];
        float theta = weights[tid*3 + 1];
        float omega = weights[tid*3 + 2];
        float ct = cosf(0.5f*theta), st = sinf(0.5f*theta);
        float ap = 0.5f*(phi + omega);
        float am = 0.5f*(phi - omega);
        float cap = cosf(ap), sap = sinf(ap);
        float cam = cosf(am), sam = sinf(am);
        sG[tid][0] = make_float2( cap*ct, -sap*ct);
        sG[tid][1] = make_float2(-cam*st, -sam*st);
        sG[tid][2] = make_float2( cam*st, -sam*st);
        sG[tid][3] = make_float2( cap*ct,  sap*ct);
    }
    __syncthreads();

    if (tid < 16) {
        const int c = tid;
        float2 col[16];
        #pragma unroll
        for (int k = 0; k < 16; k++) col[k] = make_float2(k == c ? 1.f : 0.f, 0.f);

        #pragma unroll
        for (int l = 0; l < NLAYERS; l++) {
            #pragma unroll
            for (int w = 0; w < NQ; w++) {
                float2 m00 = sG[l*NQ + w][0], m01 = sG[l*NQ + w][1];
                float2 m10 = sG[l*NQ + w][2], m11 = sG[l*NQ + w][3];
                int bit = 1 << (3 - w);
                #pragma unroll
                for (int k0 = 0; k0 < 16; k0++) {
                    if (k0 & bit) continue;
                    int k1 = k0 | bit;
                    float2 a = col[k0], b = col[k1];
                    col[k0] = make_float2(m00.x*a.x - m00.y*a.y + m01.x*b.x - m01.y*b.y,
                                          m00.x*a.y + m00.y*a.x + m01.x*b.y + m01.y*b.x);
                    col[k1] = make_float2(m10.x*a.x - m10.y*a.y + m11.x*b.x - m11.y*b.y,
                                          m10.x*a.y + m10.y*a.x + m11.x*b.y + m11.y*b.x);
                }
            }
            int r = (l % (NQ - 1)) + 1;
            #pragma unroll
            for (int w = 0; w < NQ; w++) {
                int cb = 1 << (3 - w);
                int tb = 1 << (3 - ((w + r) & 3));
                #pragma unroll
                for (int k = 0; k < 16; k++) {
                    if ((k & cb) && !(k & tb)) {
                        float2 t = col[k]; col[k] = col[k | tb]; col[k | tb] = t;
                    }
                }
            }
        }
        #pragma unroll
        for (int k = 0; k < 16; k++) sU[k][c] = col[k];
    }
    __syncthreads();

    for (int pp = tid; pp < NPAIR; pp += 128) {
        int a = 0, rem = pp;
        while (rem >= 16 - a) { rem -= 16 - a; a++; }
        int b = a + rem;

        float s[4] = {0.f, 0.f, 0.f, 0.f};
        #pragma unroll
        for (int k = 0; k < 16; k++) {
            float2 ua = sU[k][a], ub = sU[k][b];
            float re = ua.x*ub.x + ua.y*ub.y;
            #pragma unroll
            for (int i = 0; i < 4; i++)
                s[i] += ((k >> (3 - i)) & 1) ? -re : re;
        }
        float scale = (a == b) ? 1.f : 2.f;
        ulonglong2 q0, q1;
        q0.x = pack2(s[0]*scale, s[0]*scale); q0.y = pack2(s[1]*scale, s[1]*scale);
        q1.x = pack2(s[2]*scale, s[2]*scale); q1.y = pack2(s[3]*scale, s[3]*scale);
        sM[pp*2 + 0] = q0;
        sM[pp*2 + 1] = q1;
    }
    __syncthreads();

    int h = gtid & 2047;
    int j = gtid >> 11;
    int n0 = h << 1;
    int b  = n0 >> 7;
    int m  = n0 & 127;

    const ull* xp = (const ull*)(x + (size_t)b * (SEQ_LEN*CHANS)
                                   + (size_t)(j*STRIDE) * CHANS + m);
    const ull EPS2 = 0x358637bd358637bdULL;   // (1e-6f, 1e-6f)

    ull v[16];
    #pragma unroll
    for (int k = 0; k < 16; k++)
        v[k] = add2(__ldg(xp + k * (CHANS/2)), EPS2);

    ull z0 = 0ULL, z1 = 0ULL, z2 = 0ULL, z3 = 0ULL, nrm2 = 0ULL;
    int p = 0;
    #pragma unroll
    for (int a = 0; a < 16; a++) {
        #pragma unroll
        for (int bb = a; bb < 16; bb++) {
            ull u = mul2(v[a], v[bb]);
            if (bb == a) nrm2 = add2(nrm2, u);
            ulonglong2 q0 = sM[2*p + 0];
            ulonglong2 q1 = sM[2*p + 1];
            z0 = fma2(u, q0.x, z0);
            z1 = fma2(u, q0.y, z1);
            z2 = fma2(u, q1.x, z2);
            z3 = fma2(u, q1.y, z3);
            p++;
        }
    }
    ull inv2 = pack2(1.0f / lo2(nrm2), 1.0f / hi2(nrm2));

    ull* e = (ull*)(d_encT + (size_t)(j*4) * NCH + n0);
    e[0*(NCH/2)] = mul2(z0, inv2);
    e[1*(NCH/2)] = mul2(z1, inv2);
    e[2*(NCH/2)] = mul2(z2, inv2);
    e[3*(NCH/2)] = mul2(z3, inv2);
}

// ---------------------------------------------------------------------------
// Kernel B: head-GEMM over encT, added into out with PLAIN read-add-write.
// grid (12, 32, 2-channel-halves), 128 threads. Each output element is owned
// by exactly ONE thread (channel split, full k per block) -> no atomics.
// cpg = tid&15 (4 adjacent channels of the 64-channel half),
// g = tid>>4 in [0,8): 32 k each = 8 chunks. 8-way reduction (stride 65).
// ---------------------------------------------------------------------------
__global__ __launch_bounds__(128, 8) void head_add(
    const float* __restrict__ head_w,
    float* __restrict__ out)
{
    __shared__ ull sS[32 * 65];            // 16.6KB: stage (2048) / reduce (2080)

    int tid = threadIdx.x;                 // 0..127
    int o0  = blockIdx.x * 8;
    int b   = blockIdx.y;
    int ch  = blockIdx.z;                  // channel half: chans [ch*64, ch*64+64)

    // stage 256 padded head-k x 8 outputs dup-packed (2048 ull)
    #pragma unroll
    for (int it = 0; it < 16; it++) {
        int idx = it * 128 + tid;          // < 2048
        int r  = idx >> 8;
        int kk = idx & 255;
        float w = (kk < FAN_IN) ? head_w[(o0 + r) * FAN_IN + kk] : 0.f;
        sS[kk * 8 + r] = pack2(w, w);
    }
    __syncthreads();

    int cpg = tid & 15;                    // 4 channels: ch*64 + 4cpg ..+3
    int g   = tid >> 4;                    // 0..7, 32 k each

    ull acc[2][8];
    #pragma unroll
    for (int s = 0; s < 2; s++)
        #pragma unroll
        for (int r = 0; r < 8; r++) acc[s][r] = 0ULL;

    const ulonglong2* ep = (const ulonglong2*)d_encT
        + (size_t)(g * 32) * (NCH/4) + b * (CHANS/4) + ch * 16 + cpg;
    gemm_seg<NCH/4>(ep, 8, (const ulonglong2*)sS + (g * 32) * 4, acc);

    // 8-way k reduction over 32 local channel-pairs (stride 65)
    __syncthreads();
    #pragma unroll
    for (int s = 0; s < 2; s++) {
        int cp = 2 * cpg + s;              // local cp in [0,32)
        #pragma unroll
        for (int r = 0; r < 8; r++)
            sS[cp * 65 + g * 8 + r] = acc[s][r];
    }
    __syncthreads();

    // epilogue: 256 items (32 cp x 8 oo) over 128 threads -> 2 each
    int cp = tid & 31;                     // local channel pair
    int q  = tid >> 5;                     // 0..3
    #pragma unroll
    for (int t = 0; t < 2; t++) {
        int oo = 2 * q + t;
        ull s = 0ULL;
        #pragma unroll
        for (int gg = 0; gg < 8; gg++)
            s = add2(s, sS[cp * 65 + gg * 8 + oo]);
        ull* op = (ull*)out + ((size_t)b * PRED_LEN + o0 + oo) * (CHANS/2) + ch * 32 + cp;
        *op = add2(*op, s);                // exclusive owner; ordered by launch
    }
}

// ---------------------------------------------------------------------------
extern "C" void kernel_launch(void* const* d_in, const int* in_sizes, int n_in,
                              void* d_out, int out_size) {
    const float* x       = (const float*)d_in[0];
    const float* weights = (const float*)d_in[1];
    const float* head_w  = (const float*)d_in[2];
    const float* head_b  = (const float*)d_in[3];
    const float* skip_w  = (const float*)d_in[4];
    const float* skip_b  = (const float*)d_in[5];
    float* out = (float*)d_out;

    fused_enc_skip<<<SKIP_BLOCKS + ENC_BLOCKS, 128>>>(x, weights, skip_w,
                                                      head_b, skip_b, out);
    head_add<<<dim3(12, BATCH, 2), 128>>>(head_w, out);
}

// round 15
// speedup vs baseline: 1.0846x; 1.0846x over previous
#include <cuda_runtime.h>
#include <cuda_bf16.h>
#include <math.h>

// Problem constants
#define SEQ_LEN   512
#define PRED_LEN  96
#define PATCH_LEN 16
#define STRIDE    8
#define NQ        4
#define NLAYERS   3
#define NPATCH    63           // (512-16)/8+1
#define BATCH     32
#define CHANS     128
#define NCH       (BATCH*CHANS)        // 4096
#define FAN_IN    (NPATCH*NQ)          // 252
#define FPAD      256                  // head k padded to 256
#define NPAIR     136                  // 16*17/2
#define SKIP_BLOCKS (12*32)            // 384, placed FIRST in the fused grid
#define ENC_BLOCKS  504                // each handles 2 grid-stride iterations
#define ENC_ITERS   2

typedef unsigned long long ull;

// ---- packed f32x2 helpers (sm_103a) ---------------------------------------
__device__ __forceinline__ ull fma2(ull a, ull b, ull c) {
    ull d; asm("fma.rn.f32x2 %0, %1, %2, %3;" : "=l"(d) : "l"(a), "l"(b), "l"(c)); return d;
}
__device__ __forceinline__ ull mul2(ull a, ull b) {
    ull d; asm("mul.rn.f32x2 %0, %1, %2;" : "=l"(d) : "l"(a), "l"(b)); return d;
}
__device__ __forceinline__ ull add2(ull a, ull b) {
    ull d; asm("add.rn.f32x2 %0, %1, %2;" : "=l"(d) : "l"(a), "l"(b)); return d;
}
__device__ __forceinline__ ull pack2(float lo, float hi) {
    ull d; asm("mov.b64 %0, {%1, %2};" : "=l"(d) : "f"(lo), "f"(hi)); return d;
}
__device__ __forceinline__ float lo2(ull a) { return __uint_as_float((unsigned)(a & 0xffffffffull)); }
__device__ __forceinline__ float hi2(ull a) { return __uint_as_float((unsigned)(a >> 32)); }

// Scratch (device globals; no allocation allowed)
__device__ float d_encT[FPAD * NCH];    // enc transposed [f][n]; rows 252..255 zero (4MB)

// ---------------------------------------------------------------------------
// GEMM segment: LDG.128 data (4 adjacent channels per load), dup-packed
// weights via broadcast LDS.128. Per chunk (4 k): 4 LDG.128 + 16 LDS.128 +
// 64 FFMA2 => 128 MACs. STRIDE_U2 = row stride in ulonglong2 (compile-time).
// ---------------------------------------------------------------------------
template<int STRIDE_U2>
__device__ __forceinline__ void gemm_seg(const ulonglong2* __restrict__ p, int nchunks,
                                         const ulonglong2* __restrict__ sw,
                                         ull acc[2][8]) {
    #pragma unroll 1
    for (int c = 0; c < nchunks; c++) {
        ulonglong2 V[4];
        #pragma unroll
        for (int i = 0; i < 4; i++)
            V[i] = __ldg(p + i * STRIDE_U2);
        #pragma unroll
        for (int i = 0; i < 4; i++) {
            ull v0 = V[i].x, v1 = V[i].y;
            #pragma unroll
            for (int j = 0; j < 4; j++) {
                ulonglong2 q = sw[i*4 + j];
                acc[0][2*j]   = fma2(v0, q.x, acc[0][2*j]);
                acc[0][2*j+1] = fma2(v0, q.y, acc[0][2*j+1]);
                acc[1][2*j]   = fma2(v1, q.x, acc[1][2*j]);
                acc[1][2*j+1] = fma2(v1, q.y, acc[1][2*j+1]);
            }
        }
        p  += 4 * STRIDE_U2;
        sw += 16;
    }
}

// ---------------------------------------------------------------------------
// Kernel A: heterogeneous fused launch (128-thread blocks, 888 total = 1 wave).
//   blocks [0, 384):   skip-GEMM, full 512 k; writes out = skip + biases.
//   blocks [384, 888): encoder, 2 grid-stride iterations each.
// ---------------------------------------------------------------------------
__global__ __launch_bounds__(128, 8) void fused_enc_skip(
    const float* __restrict__ x,
    const float* __restrict__ weights,
    const float* __restrict__ skip_w,
    const float* __restrict__ head_b,
    const float* __restrict__ skip_b,
    float* __restrict__ out)
{
    __shared__ float2 sG[12][4];
    __shared__ float2 sU[16][16];
    __shared__ ulonglong2 sM[NPAIR * 2];
    __shared__ ull sS[64 * 33];            // 16.5KB: stage (2048/pass) / reduce (2112)

    int tid = threadIdx.x;                 // 0..127

    if (blockIdx.x < SKIP_BLOCKS) {
        // =================== SKIP-GEMM (full k) ===================
        int ot = blockIdx.x % 12;
        int b  = blockIdx.x / 12;
        int o0 = ot * 8;

        int cpg = tid & 31;                // 4 channels: 4cpg..4cpg+3
        int g   = tid >> 5;                // 0..3

        ull acc[2][8];
        #pragma unroll
        for (int s = 0; s < 2; s++)
            #pragma unroll
            for (int r = 0; r < 8; r++) acc[s][r] = 0ULL;

        #pragma unroll 1
        for (int pass = 0; pass < 2; pass++) {
            #pragma unroll
            for (int it = 0; it < 16; it++) {
                int idx = it * 128 + tid;  // < 2048
                int r  = idx >> 8;
                int kk = idx & 255;
                float w = skip_w[(o0 + r) * SEQ_LEN + pass * 256 + kk];
                sS[kk * 8 + r] = pack2(w, w);
            }
            __syncthreads();

            const ulonglong2* xp = (const ulonglong2*)x
                + ((size_t)b * SEQ_LEN + pass * 256 + g * 64) * (CHANS/4) + cpg;
            gemm_seg<CHANS/4>(xp, 16, (const ulonglong2*)sS + (g * 64) * 4, acc);
            __syncthreads();
        }

        #pragma unroll
        for (int s = 0; s < 2; s++) {
            int cp = 2 * cpg + s;
            #pragma unroll
            for (int r = 0; r < 8; r++)
                sS[cp * 33 + g * 8 + r] = acc[s][r];
        }
        __syncthreads();

        int cp = tid & 63;
        int q  = tid >> 6;                 // 0..1
        #pragma unroll
        for (int t = 0; t < 4; t++) {
            int oo = 4 * q + t;
            ull s = add2(add2(sS[cp*33 + 0*8 + oo], sS[cp*33 + 1*8 + oo]),
                         add2(sS[cp*33 + 2*8 + oo], sS[cp*33 + 3*8 + oo]));
            float bias = head_b[o0 + oo] + skip_b[o0 + oo];
            s = add2(s, pack2(bias, bias));
            ((ull*)out)[((size_t)b * PRED_LEN + o0 + oo) * (CHANS/2) + cp] = s;
        }
        return;
    }

    // ======================= ENCODER =======================
    int ebid = blockIdx.x - SKIP_BLOCKS;   // 0..503

    if (tid < 12) {
        float phi   = weights[tid*3 + 0];
        float theta = weights[tid*3 + 1];
        float omega = weights[tid*3 + 2];
        float ct = cosf(0.5f*theta), st = sinf(0.5f*theta);
        float ap = 0.5f*(phi + omega);
        float am = 0.5f*(phi - omega);
        float cap = cosf(ap), sap = sinf(ap);
        float cam = cosf(am), sam = sinf(am);
        sG[tid][0] = make_float2( cap*ct, -sap*ct);
        sG[tid][1] = make_float2(-cam*st, -sam*st);
        sG[tid][2] = make_float2( cam*st, -sam*st);
        sG[tid][3] = make_float2( cap*ct,  sap*ct);
    }
    __syncthreads();

    if (tid < 16) {
        const int c = tid;
        float2 col[16];
        #pragma unroll
        for (int k = 0; k < 16; k++) col[k] = make_float2(k == c ? 1.f : 0.f, 0.f);

        #pragma unroll
        for (int l = 0; l < NLAYERS; l++) {
            #pragma unroll
            for (int w = 0; w < NQ; w++) {
                float2 m00 = sG[l*NQ + w][0], m01 = sG[l*NQ + w][1];
                float2 m10 = sG[l*NQ + w][2], m11 = sG[l*NQ + w][3];
                int bit = 1 << (3 - w);
                #pragma unroll
                for (int k0 = 0; k0 < 16; k0++) {
                    if (k0 & bit) continue;
                    int k1 = k0 | bit;
                    float2 a = col[k0], b = col[k1];
                    col[k0] = make_float2(m00.x*a.x - m00.y*a.y + m01.x*b.x - m01.y*b.y,
                                          m00.x*a.y + m00.y*a.x + m01.x*b.y + m01.y*b.x);
                    col[k1] = make_float2(m10.x*a.x - m10.y*a.y + m11.x*b.x - m11.y*b.y,
                                          m10.x*a.y + m10.y*a.x + m11.x*b.y + m11.y*b.x);
                }
            }
            int r = (l % (NQ - 1)) + 1;
            #pragma unroll
            for (int w = 0; w < NQ; w++) {
                int cb = 1 << (3 - w);
                int tb = 1 << (3 - ((w + r) & 3));
                #pragma unroll
                for (int k = 0; k < 16; k++) {
                    if ((k & cb) && !(k & tb)) {
                        float2 t = col[k]; col[k] = col[k | tb]; col[k | tb] = t;
                    }
                }
            }
        }
        #pragma unroll
        for (int k = 0; k < 16; k++) sU[k][c] = col[k];
    }
    __syncthreads();

    for (int pp = tid; pp < NPAIR; pp += 128) {
        int a = 0, rem = pp;
        while (rem >= 16 - a) { rem -= 16 - a; a++; }
        int b = a + rem;

        float s[4] = {0.f, 0.f, 0.f, 0.f};
        #pragma unroll
        for (int k = 0; k < 16; k++) {
            float2 ua = sU[k][a], ub = sU[k][b];
            float re = ua.x*ub.x + ua.y*ub.y;
            #pragma unroll
            for (int i = 0; i < 4; i++)
                s[i] += ((k >> (3 - i)) & 1) ? -re : re;
        }
        float scale = (a == b) ? 1.f : 2.f;
        ulonglong2 q0, q1;
        q0.x = pack2(s[0]*scale, s[0]*scale); q0.y = pack2(s[1]*scale, s[1]*scale);
        q1.x = pack2(s[2]*scale, s[2]*scale); q1.y = pack2(s[3]*scale, s[3]*scale);
        sM[pp*2 + 0] = q0;
        sM[pp*2 + 1] = q1;
    }
    __syncthreads();

    #pragma unroll 1
    for (int it = 0; it < ENC_ITERS; it++) {
        int gtid = (ebid * ENC_ITERS + it) * 128 + tid;   // < 129024

        // zero the 4 pad rows of encT (rows 252..255 = 8192 ull)
        if (gtid < 8192)
            ((ull*)(d_encT + (size_t)FAN_IN * NCH))[gtid] = 0ULL;

        int h = gtid & 2047;
        int j = gtid >> 11;
        int n0 = h << 1;
        int b  = n0 >> 7;
        int m  = n0 & 127;

        const ull* xp = (const ull*)(x + (size_t)b * (SEQ_LEN*CHANS)
                                       + (size_t)(j*STRIDE) * CHANS + m);
        const ull EPS2 = 0x358637bd358637bdULL;   // (1e-6f, 1e-6f)

        ull v[16];
        #pragma unroll
        for (int k = 0; k < 16; k++)
            v[k] = add2(__ldg(xp + k * (CHANS/2)), EPS2);

        ull z0 = 0ULL, z1 = 0ULL, z2 = 0ULL, z3 = 0ULL, nrm2 = 0ULL;
        int p = 0;
        #pragma unroll
        for (int a = 0; a < 16; a++) {
            #pragma unroll
            for (int bb = a; bb < 16; bb++) {
                ull u = mul2(v[a], v[bb]);
                if (bb == a) nrm2 = add2(nrm2, u);
                ulonglong2 q0 = sM[2*p + 0];
                ulonglong2 q1 = sM[2*p + 1];
                z0 = fma2(u, q0.x, z0);
                z1 = fma2(u, q0.y, z1);
                z2 = fma2(u, q1.x, z2);
                z3 = fma2(u, q1.y, z3);
                p++;
            }
        }
        ull inv2 = pack2(1.0f / lo2(nrm2), 1.0f / hi2(nrm2));

        ull* e = (ull*)(d_encT + (size_t)(j*4) * NCH + n0);
        e[0*(NCH/2)] = mul2(z0, inv2);
        e[1*(NCH/2)] = mul2(z1, inv2);
        e[2*(NCH/2)] = mul2(z2, inv2);
        e[3*(NCH/2)] = mul2(z3, inv2);
    }
}

// ---------------------------------------------------------------------------
// Kernel B: head-GEMM over encT (full padded 256 k), added into out with
// plain read-add-write (exclusive owner per element; ordered by launch).
// grid (12, 32), 256 threads: cpg=tid&31 (4 adjacent channels), g=tid>>5 in
// [0,8) = 32 k each (8 chunks). 8-way k reduction (stride 65).
// ---------------------------------------------------------------------------
__global__ __launch_bounds__(256, 4) void head_final(
    const float* __restrict__ head_w,
    float* __restrict__ out)
{
    __shared__ ull sS[64 * 65];            // 33.3KB: stage (2048) / reduce (4160)

    int tid = threadIdx.x;                 // 0..255
    int o0  = blockIdx.x * 8;
    int b   = blockIdx.y;

    // stage 256 padded head-k x 8 outputs dup-packed
    #pragma unroll
    for (int it = 0; it < 8; it++) {
        int idx = it * 256 + tid;          // < 2048
        int r  = idx >> 8;
        int kk = idx & 255;
        float w = (kk < FAN_IN) ? head_w[(o0 + r) * FAN_IN + kk] : 0.f;
        sS[kk * 8 + r] = pack2(w, w);
    }
    __syncthreads();

    int cpg = tid & 31;                    // 4 channels: 4cpg..4cpg+3
    int g   = tid >> 5;                    // 0..7, 32 k each = 8 chunks

    ull acc[2][8];
    #pragma unroll
    for (int s = 0; s < 2; s++)
        #pragma unroll
        for (int r = 0; r < 8; r++) acc[s][r] = 0ULL;

    const ulonglong2* ep = (const ulonglong2*)d_encT
        + (size_t)(g * 32) * (NCH/4) + b * (CHANS/4) + cpg;
    gemm_seg<NCH/4>(ep, 8, (const ulonglong2*)sS + (g * 32) * 4, acc);

    // 8-way k reduction (stride 65)
    __syncthreads();
    #pragma unroll
    for (int s = 0; s < 2; s++) {
        int cp = 2 * cpg + s;              // 0..63
        #pragma unroll
        for (int r = 0; r < 8; r++)
            sS[cp * 65 + g * 8 + r] = acc[s][r];
    }
    __syncthreads();

    int cp = tid & 63;
    int q  = tid >> 6;                     // 0..3
    #pragma unroll
    for (int t = 0; t < 2; t++) {
        int oo = 2 * q + t;
        ull s = 0ULL;
        #pragma unroll
        for (int gg = 0; gg < 8; gg++)
            s = add2(s, sS[cp * 65 + gg * 8 + oo]);
        ull* op = (ull*)out + ((size_t)b * PRED_LEN + o0 + oo) * (CHANS/2) + cp;
        *op = add2(*op, s);                // exclusive owner; ordered by launch
    }
}

// ---------------------------------------------------------------------------
extern "C" void kernel_launch(void* const* d_in, const int* in_sizes, int n_in,
                              void* d_out, int out_size) {
    const float* x       = (const float*)d_in[0];
    const float* weights = (const float*)d_in[1];
    const float* head_w  = (const float*)d_in[2];
    const float* head_b  = (const float*)d_in[3];
    const float* skip_w  = (const float*)d_in[4];
    const float* skip_b  = (const float*)d_in[5];
    float* out = (float*)d_out;

    fused_enc_skip<<<SKIP_BLOCKS + ENC_BLOCKS, 128>>>(x, weights, skip_w,
                                                      head_b, skip_b, out);
    head_final<<<dim3(12, BATCH), 256>>>(head_w, out);
}

// round 16
// speedup vs baseline: 1.1329x; 1.0445x over previous
#include <cuda_runtime.h>
#include <cuda_bf16.h>
#include <math.h>

// Problem constants
#define SEQ_LEN   512
#define PRED_LEN  96
#define PATCH_LEN 16
#define STRIDE    8
#define NQ        4
#define NLAYERS   3
#define NPATCH    63           // (512-16)/8+1
#define BATCH     32
#define CHANS     128
#define NCH       (BATCH*CHANS)        // 4096
#define FAN_IN    (NPATCH*NQ)          // 252
#define FPAD      256                  // head k padded to 256
#define NPAIR     136                  // 16*17/2
#define SKIP_BLOCKS (12*32)            // 384, placed FIRST in the fused grid
#define ENC_BLOCKS  504                // each handles 2 grid-stride iterations
#define ENC_ITERS   2

typedef unsigned long long ull;

// ---- packed f32x2 helpers (sm_103a) ---------------------------------------
__device__ __forceinline__ ull fma2(ull a, ull b, ull c) {
    ull d; asm("fma.rn.f32x2 %0, %1, %2, %3;" : "=l"(d) : "l"(a), "l"(b), "l"(c)); return d;
}
__device__ __forceinline__ ull mul2(ull a, ull b) {
    ull d; asm("mul.rn.f32x2 %0, %1, %2;" : "=l"(d) : "l"(a), "l"(b)); return d;
}
__device__ __forceinline__ ull add2(ull a, ull b) {
    ull d; asm("add.rn.f32x2 %0, %1, %2;" : "=l"(d) : "l"(a), "l"(b)); return d;
}
__device__ __forceinline__ ull pack2(float lo, float hi) {
    ull d; asm("mov.b64 %0, {%1, %2};" : "=l"(d) : "f"(lo), "f"(hi)); return d;
}
__device__ __forceinline__ float lo2(ull a) { return __uint_as_float((unsigned)(a & 0xffffffffull)); }
__device__ __forceinline__ float hi2(ull a) { return __uint_as_float((unsigned)(a >> 32)); }

// Scratch (device globals; no allocation allowed)
__device__ float d_encT[FPAD * NCH];    // enc transposed [f][n]; rows 252..255 zero (4MB)

// ---------------------------------------------------------------------------
// GEMM segment, 8-k chunks: 8 front-batched LDG.128 (MLP=8/thread) then
// 8 x (4 broadcast LDS.128 + 16 FFMA2). Per chunk: 8 LDG + 32 LDS + 128 FFMA2
// => 256 MACs. STRIDE_U2 = row stride in ulonglong2 (compile-time).
// ---------------------------------------------------------------------------
template<int STRIDE_U2>
__device__ __forceinline__ void gemm_seg8(const ulonglong2* __restrict__ p, int nchunks,
                                          const ulonglong2* __restrict__ sw,
                                          ull acc[2][8]) {
    #pragma unroll 1
    for (int c = 0; c < nchunks; c++) {
        ulonglong2 V[8];
        #pragma unroll
        for (int i = 0; i < 8; i++)
            V[i] = __ldg(p + i * STRIDE_U2);
        #pragma unroll
        for (int i = 0; i < 8; i++) {
            ull v0 = V[i].x, v1 = V[i].y;
            #pragma unroll
            for (int j = 0; j < 4; j++) {
                ulonglong2 q = sw[i*4 + j];
                acc[0][2*j]   = fma2(v0, q.x, acc[0][2*j]);
                acc[0][2*j+1] = fma2(v0, q.y, acc[0][2*j+1]);
                acc[1][2*j]   = fma2(v1, q.x, acc[1][2*j]);
                acc[1][2*j+1] = fma2(v1, q.y, acc[1][2*j+1]);
            }
        }
        p  += 8 * STRIDE_U2;
        sw += 32;
    }
}

// ---------------------------------------------------------------------------
// Kernel A: heterogeneous fused launch (128-thread blocks, 888 total = 1 wave).
//   blocks [0, 384):   skip-GEMM, full 512 k; writes out = skip + biases.
//   blocks [384, 888): encoder, 2 grid-stride iterations each.
// ---------------------------------------------------------------------------
__global__ __launch_bounds__(128, 8) void fused_enc_skip(
    const float* __restrict__ x,
    const float* __restrict__ weights,
    const float* __restrict__ skip_w,
    const float* __restrict__ head_b,
    const float* __restrict__ skip_b,
    float* __restrict__ out)
{
    __shared__ float2 sG[12][4];
    __shared__ float2 sU[16][16];
    __shared__ ulonglong2 sM[NPAIR * 2];
    __shared__ ull sS[64 * 33];            // 16.5KB: stage (2048/pass) / reduce (2112)

    int tid = threadIdx.x;                 // 0..127

    if (blockIdx.x < SKIP_BLOCKS) {
        // =================== SKIP-GEMM (full k) ===================
        int ot = blockIdx.x % 12;
        int b  = blockIdx.x / 12;
        int o0 = ot * 8;

        int cpg = tid & 31;                // 4 channels: 4cpg..4cpg+3
        int g   = tid >> 5;                // 0..3

        ull acc[2][8];
        #pragma unroll
        for (int s = 0; s < 2; s++)
            #pragma unroll
            for (int r = 0; r < 8; r++) acc[s][r] = 0ULL;

        #pragma unroll 1
        for (int pass = 0; pass < 2; pass++) {
            #pragma unroll
            for (int it = 0; it < 16; it++) {
                int idx = it * 128 + tid;  // < 2048
                int r  = idx >> 8;
                int kk = idx & 255;
                float w = skip_w[(o0 + r) * SEQ_LEN + pass * 256 + kk];
                sS[kk * 8 + r] = pack2(w, w);
            }
            __syncthreads();

            const ulonglong2* xp = (const ulonglong2*)x
                + ((size_t)b * SEQ_LEN + pass * 256 + g * 64) * (CHANS/4) + cpg;
            gemm_seg8<CHANS/4>(xp, 8, (const ulonglong2*)sS + (g * 64) * 4, acc);
            __syncthreads();
        }

        #pragma unroll
        for (int s = 0; s < 2; s++) {
            int cp = 2 * cpg + s;
            #pragma unroll
            for (int r = 0; r < 8; r++)
                sS[cp * 33 + g * 8 + r] = acc[s][r];
        }
        __syncthreads();

        int cp = tid & 63;
        int q  = tid >> 6;                 // 0..1
        #pragma unroll
        for (int t = 0; t < 4; t++) {
            int oo = 4 * q + t;
            ull s = add2(add2(sS[cp*33 + 0*8 + oo], sS[cp*33 + 1*8 + oo]),
                         add2(sS[cp*33 + 2*8 + oo], sS[cp*33 + 3*8 + oo]));
            float bias = head_b[o0 + oo] + skip_b[o0 + oo];
            s = add2(s, pack2(bias, bias));
            ((ull*)out)[((size_t)b * PRED_LEN + o0 + oo) * (CHANS/2) + cp] = s;
        }
        return;
    }

    // ======================= ENCODER =======================
    int ebid = blockIdx.x - SKIP_BLOCKS;   // 0..503

    if (tid < 12) {
        float phi   = weights[tid*3 + 0];
        float theta = weights[tid*3 + 1];
        float omega = weights[tid*3 + 2];
        float ct = cosf(0.5f*theta), st = sinf(0.5f*theta);
        float ap = 0.5f*(phi + omega);
        float am = 0.5f*(phi - omega);
        float cap = cosf(ap), sap = sinf(ap);
        float cam = cosf(am), sam = sinf(am);
        sG[tid][0] = make_float2( cap*ct, -sap*ct);
        sG[tid][1] = make_float2(-cam*st, -sam*st);
        sG[tid][2] = make_float2( cam*st, -sam*st);
        sG[tid][3] = make_float2( cap*ct,  sap*ct);
    }
    __syncthreads();

    if (tid < 16) {
        const int c = tid;
        float2 col[16];
        #pragma unroll
        for (int k = 0; k < 16; k++) col[k] = make_float2(k == c ? 1.f : 0.f, 0.f);

        #pragma unroll
        for (int l = 0; l < NLAYERS; l++) {
            #pragma unroll
            for (int w = 0; w < NQ; w++) {
                float2 m00 = sG[l*NQ + w][0], m01 = sG[l*NQ + w][1];
                float2 m10 = sG[l*NQ + w][2], m11 = sG[l*NQ + w][3];
                int bit = 1 << (3 - w);
                #pragma unroll
                for (int k0 = 0; k0 < 16; k0++) {
                    if (k0 & bit) continue;
                    int k1 = k0 | bit;
                    float2 a = col[k0], b = col[k1];
                    col[k0] = make_float2(m00.x*a.x - m00.y*a.y + m01.x*b.x - m01.y*b.y,
                                          m00.x*a.y + m00.y*a.x + m01.x*b.y + m01.y*b.x);
                    col[k1] = make_float2(m10.x*a.x - m10.y*a.y + m11.x*b.x - m11.y*b.y,
                                          m10.x*a.y + m10.y*a.x + m11.x*b.y + m11.y*b.x);
                }
            }
            int r = (l % (NQ - 1)) + 1;
            #pragma unroll
            for (int w = 0; w < NQ; w++) {
                int cb = 1 << (3 - w);
                int tb = 1 << (3 - ((w + r) & 3));
                #pragma unroll
                for (int k = 0; k < 16; k++) {
                    if ((k & cb) && !(k & tb)) {
                        float2 t = col[k]; col[k] = col[k | tb]; col[k | tb] = t;
                    }
                }
            }
        }
        #pragma unroll
        for (int k = 0; k < 16; k++) sU[k][c] = col[k];
    }
    __syncthreads();

    for (int pp = tid; pp < NPAIR; pp += 128) {
        int a = 0, rem = pp;
        while (rem >= 16 - a) { rem -= 16 - a; a++; }
        int b = a + rem;

        float s[4] = {0.f, 0.f, 0.f, 0.f};
        #pragma unroll
        for (int k = 0; k < 16; k++) {
            float2 ua = sU[k][a], ub = sU[k][b];
            float re = ua.x*ub.x + ua.y*ub.y;
            #pragma unroll
            for (int i = 0; i < 4; i++)
                s[i] += ((k >> (3 - i)) & 1) ? -re : re;
        }
        float scale = (a == b) ? 1.f : 2.f;
        ulonglong2 q0, q1;
        q0.x = pack2(s[0]*scale, s[0]*scale); q0.y = pack2(s[1]*scale, s[1]*scale);
        q1.x = pack2(s[2]*scale, s[2]*scale); q1.y = pack2(s[3]*scale, s[3]*scale);
        sM[pp*2 + 0] = q0;
        sM[pp*2 + 1] = q1;
    }
    __syncthreads();

    #pragma unroll 1
    for (int it = 0; it < ENC_ITERS; it++) {
        int gtid = (ebid * ENC_ITERS + it) * 128 + tid;   // < 129024

        // zero the 4 pad rows of encT (rows 252..255 = 8192 ull)
        if (gtid < 8192)
            ((ull*)(d_encT + (size_t)FAN_IN * NCH))[gtid] = 0ULL;

        int h = gtid & 2047;
        int j = gtid >> 11;
        int n0 = h << 1;
        int b  = n0 >> 7;
        int m  = n0 & 127;

        const ull* xp = (const ull*)(x + (size_t)b * (SEQ_LEN*CHANS)
                                       + (size_t)(j*STRIDE) * CHANS + m);
        const ull EPS2 = 0x358637bd358637bdULL;   // (1e-6f, 1e-6f)

        ull v[16];
        #pragma unroll
        for (int k = 0; k < 16; k++)
            v[k] = add2(__ldg(xp + k * (CHANS/2)), EPS2);

        ull z0 = 0ULL, z1 = 0ULL, z2 = 0ULL, z3 = 0ULL, nrm2 = 0ULL;
        int p = 0;
        #pragma unroll
        for (int a = 0; a < 16; a++) {
            #pragma unroll
            for (int bb = a; bb < 16; bb++) {
                ull u = mul2(v[a], v[bb]);
                if (bb == a) nrm2 = add2(nrm2, u);
                ulonglong2 q0 = sM[2*p + 0];
                ulonglong2 q1 = sM[2*p + 1];
                z0 = fma2(u, q0.x, z0);
                z1 = fma2(u, q0.y, z1);
                z2 = fma2(u, q1.x, z2);
                z3 = fma2(u, q1.y, z3);
                p++;
            }
        }
        ull inv2 = pack2(1.0f / lo2(nrm2), 1.0f / hi2(nrm2));

        ull* e = (ull*)(d_encT + (size_t)(j*4) * NCH + n0);
        e[0*(NCH/2)] = mul2(z0, inv2);
        e[1*(NCH/2)] = mul2(z1, inv2);
        e[2*(NCH/2)] = mul2(z2, inv2);
        e[3*(NCH/2)] = mul2(z3, inv2);
    }
}

// ---------------------------------------------------------------------------
// Kernel B: head-GEMM over encT (full padded 256 k), added into out with
// plain read-add-write (exclusive owner per element; ordered by launch).
// grid (12, 32), 256 threads: cpg=tid&31 (4 adjacent channels), g=tid>>5 in
// [0,8) = 32 k each (4 chunks of 8). 8-way k reduction (stride 65).
// ---------------------------------------------------------------------------
__global__ __launch_bounds__(256, 4) void head_final(
    const float* __restrict__ head_w,
    float* __restrict__ out)
{
    __shared__ ull sS[64 * 65];            // 33.3KB: stage (2048) / reduce (4160)

    int tid = threadIdx.x;                 // 0..255
    int o0  = blockIdx.x * 8;
    int b   = blockIdx.y;

    // stage 256 padded head-k x 8 outputs dup-packed
    #pragma unroll
    for (int it = 0; it < 8; it++) {
        int idx = it * 256 + tid;          // < 2048
        int r  = idx >> 8;
        int kk = idx & 255;
        float w = (kk < FAN_IN) ? head_w[(o0 + r) * FAN_IN + kk] : 0.f;
        sS[kk * 8 + r] = pack2(w, w);
    }
    __syncthreads();

    int cpg = tid & 31;                    // 4 channels: 4cpg..4cpg+3
    int g   = tid >> 5;                    // 0..7, 32 k each = 4 chunks of 8

    ull acc[2][8];
    #pragma unroll
    for (int s = 0; s < 2; s++)
        #pragma unroll
        for (int r = 0; r < 8; r++) acc[s][r] = 0ULL;

    const ulonglong2* ep = (const ulonglong2*)d_encT
        + (size_t)(g * 32) * (NCH/4) + b * (CHANS/4) + cpg;
    gemm_seg8<NCH/4>(ep, 4, (const ulonglong2*)sS + (g * 32) * 4, acc);

    // 8-way k reduction (stride 65)
    __syncthreads();
    #pragma unroll
    for (int s = 0; s < 2; s++) {
        int cp = 2 * cpg + s;              // 0..63
        #pragma unroll
        for (int r = 0; r < 8; r++)
            sS[cp * 65 + g * 8 + r] = acc[s][r];
    }
    __syncthreads();

    int cp = tid & 63;
    int q  = tid >> 6;                     // 0..3
    #pragma unroll
    for (int t = 0; t < 2; t++) {
        int oo = 2 * q + t;
        ull s = 0ULL;
        #pragma unroll
        for (int gg = 0; gg < 8; gg++)
            s = add2(s, sS[cp * 65 + gg * 8 + oo]);
        ull* op = (ull*)out + ((size_t)b * PRED_LEN + o0 + oo) * (CHANS/2) + cp;
        *op = add2(*op, s);                // exclusive owner; ordered by launch
    }
}

// ---------------------------------------------------------------------------
extern "C" void kernel_launch(void* const* d_in, const int* in_sizes, int n_in,
                              void* d_out, int out_size) {
    const float* x       = (const float*)d_in[0];
    const float* weights = (const float*)d_in[1];
    const float* head_w  = (const float*)d_in[2];
    const float* head_b  = (const float*)d_in[3];
    const float* skip_w  = (const float*)d_in[4];
    const float* skip_b  = (const float*)d_in[5];
    float* out = (float*)d_out;

    fused_enc_skip<<<SKIP_BLOCKS + ENC_BLOCKS, 128>>>(x, weights, skip_w,
                                                      head_b, skip_b, out);
    head_final<<<dim3(12, BATCH), 256>>>(head_w, out);
}

// round 17
// speedup vs baseline: 1.1605x; 1.0244x over previous
#include <cuda_runtime.h>
#include <cuda_bf16.h>
#include <math.h>

// Problem constants
#define SEQ_LEN   512
#define PRED_LEN  96
#define PATCH_LEN 16
#define STRIDE    8
#define NQ        4
#define NLAYERS   3
#define NPATCH    63           // (512-16)/8+1
#define BATCH     32
#define CHANS     128
#define NCH       (BATCH*CHANS)        // 4096
#define FAN_IN    (NPATCH*NQ)          // 252
#define FPAD      256                  // head k padded to 256
#define NPAIR     136                  // 16*17/2
#define SKIP_BLOCKS (12*32)            // 384, placed FIRST in the fused grid
#define ENC_BLOCKS  252                // each: 2 iterations of 128 4-channel units
#define ENC_ITERS   2

typedef unsigned long long ull;

// ---- packed f32x2 helpers (sm_103a) ---------------------------------------
__device__ __forceinline__ ull fma2(ull a, ull b, ull c) {
    ull d; asm("fma.rn.f32x2 %0, %1, %2, %3;" : "=l"(d) : "l"(a), "l"(b), "l"(c)); return d;
}
__device__ __forceinline__ ull mul2(ull a, ull b) {
    ull d; asm("mul.rn.f32x2 %0, %1, %2;" : "=l"(d) : "l"(a), "l"(b)); return d;
}
__device__ __forceinline__ ull add2(ull a, ull b) {
    ull d; asm("add.rn.f32x2 %0, %1, %2;" : "=l"(d) : "l"(a), "l"(b)); return d;
}
__device__ __forceinline__ ull pack2(float lo, float hi) {
    ull d; asm("mov.b64 %0, {%1, %2};" : "=l"(d) : "f"(lo), "f"(hi)); return d;
}
__device__ __forceinline__ float lo2(ull a) { return __uint_as_float((unsigned)(a & 0xffffffffull)); }
__device__ __forceinline__ float hi2(ull a) { return __uint_as_float((unsigned)(a >> 32)); }

// Scratch (device globals; no allocation allowed)
__device__ float d_encT[FPAD * NCH];    // enc transposed [f][n]; rows 252..255 zero (4MB)

// ---------------------------------------------------------------------------
// GEMM segment, 8-k chunks: 8 front-batched LDG.128 (MLP=8/thread) then
// 8 x (4 broadcast LDS.128 + 16 FFMA2). STRIDE_U2 in ulonglong2 units.
// ---------------------------------------------------------------------------
template<int STRIDE_U2>
__device__ __forceinline__ void gemm_seg8(const ulonglong2* __restrict__ p, int nchunks,
                                          const ulonglong2* __restrict__ sw,
                                          ull acc[2][8]) {
    #pragma unroll 1
    for (int c = 0; c < nchunks; c++) {
        ulonglong2 V[8];
        #pragma unroll
        for (int i = 0; i < 8; i++)
            V[i] = __ldg(p + i * STRIDE_U2);
        #pragma unroll
        for (int i = 0; i < 8; i++) {
            ull v0 = V[i].x, v1 = V[i].y;
            #pragma unroll
            for (int j = 0; j < 4; j++) {
                ulonglong2 q = sw[i*4 + j];
                acc[0][2*j]   = fma2(v0, q.x, acc[0][2*j]);
                acc[0][2*j+1] = fma2(v0, q.y, acc[0][2*j+1]);
                acc[1][2*j]   = fma2(v1, q.x, acc[1][2*j]);
                acc[1][2*j+1] = fma2(v1, q.y, acc[1][2*j+1]);
            }
        }
        p  += 8 * STRIDE_U2;
        sw += 32;
    }
}

// ---------------------------------------------------------------------------
// Kernel A: heterogeneous fused launch (128-thread blocks, 636 total; single
// wave at 5 blocks/SM).
//   blocks [0, 384):   skip-GEMM, full 512 k; writes out = skip + biases.
//   blocks [384, 636): encoder, 4 channels/thread (two f32x2 streams share
//                      every sM load -> enc LDS halved), 2 iterations each.
// ---------------------------------------------------------------------------
__global__ __launch_bounds__(128, 5) void fused_enc_skip(
    const float* __restrict__ x,
    const float* __restrict__ weights,
    const float* __restrict__ skip_w,
    const float* __restrict__ head_b,
    const float* __restrict__ skip_b,
    float* __restrict__ out)
{
    __shared__ float2 sG[12][4];
    __shared__ float2 sU[16][16];
    __shared__ ulonglong2 sM[NPAIR * 2];
    __shared__ ull sS[64 * 33];            // 16.5KB: stage (2048/pass) / reduce (2112)

    int tid = threadIdx.x;                 // 0..127

    if (blockIdx.x < SKIP_BLOCKS) {
        // =================== SKIP-GEMM (full k) ===================
        int ot = blockIdx.x % 12;
        int b  = blockIdx.x / 12;
        int o0 = ot * 8;

        int cpg = tid & 31;                // 4 channels: 4cpg..4cpg+3
        int g   = tid >> 5;                // 0..3

        ull acc[2][8];
        #pragma unroll
        for (int s = 0; s < 2; s++)
            #pragma unroll
            for (int r = 0; r < 8; r++) acc[s][r] = 0ULL;

        #pragma unroll 1
        for (int pass = 0; pass < 2; pass++) {
            #pragma unroll
            for (int it = 0; it < 16; it++) {
                int idx = it * 128 + tid;  // < 2048
                int r  = idx >> 8;
                int kk = idx & 255;
                float w = skip_w[(o0 + r) * SEQ_LEN + pass * 256 + kk];
                sS[kk * 8 + r] = pack2(w, w);
            }
            __syncthreads();

            const ulonglong2* xp = (const ulonglong2*)x
                + ((size_t)b * SEQ_LEN + pass * 256 + g * 64) * (CHANS/4) + cpg;
            gemm_seg8<CHANS/4>(xp, 8, (const ulonglong2*)sS + (g * 64) * 4, acc);
            __syncthreads();
        }

        #pragma unroll
        for (int s = 0; s < 2; s++) {
            int cp = 2 * cpg + s;
            #pragma unroll
            for (int r = 0; r < 8; r++)
                sS[cp * 33 + g * 8 + r] = acc[s][r];
        }
        __syncthreads();

        int cp = tid & 63;
        int q  = tid >> 6;                 // 0..1
        #pragma unroll
        for (int t = 0; t < 4; t++) {
            int oo = 4 * q + t;
            ull s = add2(add2(sS[cp*33 + 0*8 + oo], sS[cp*33 + 1*8 + oo]),
                         add2(sS[cp*33 + 2*8 + oo], sS[cp*33 + 3*8 + oo]));
            float bias = head_b[o0 + oo] + skip_b[o0 + oo];
            s = add2(s, pack2(bias, bias));
            ((ull*)out)[((size_t)b * PRED_LEN + o0 + oo) * (CHANS/2) + cp] = s;
        }
        return;
    }

    // ======================= ENCODER =======================
    int ebid = blockIdx.x - SKIP_BLOCKS;   // 0..251

    if (tid < 12) {
        float phi   = weights[tid*3 + 0];
        float theta = weights[tid*3 + 1];
        float omega = weights[tid*3 + 2];
        float ct = cosf(0.5f*theta), st = sinf(0.5f*theta);
        float ap = 0.5f*(phi + omega);
        float am = 0.5f*(phi - omega);
        float cap = cosf(ap), sap = sinf(ap);
        float cam = cosf(am), sam = sinf(am);
        sG[tid][0] = make_float2( cap*ct, -sap*ct);
        sG[tid][1] = make_float2(-cam*st, -sam*st);
        sG[tid][2] = make_float2( cam*st, -sam*st);
        sG[tid][3] = make_float2( cap*ct,  sap*ct);
    }
    __syncthreads();

    if (tid < 16) {
        const int c = tid;
        float2 col[16];
        #pragma unroll
        for (int k = 0; k < 16; k++) col[k] = make_float2(k == c ? 1.f : 0.f, 0.f);

        #pragma unroll
        for (int l = 0; l < NLAYERS; l++) {
            #pragma unroll
            for (int w = 0; w < NQ; w++) {
                float2 m00 = sG[l*NQ + w][0], m01 = sG[l*NQ + w][1];
                float2 m10 = sG[l*NQ + w][2], m11 = sG[l*NQ + w][3];
                int bit = 1 << (3 - w);
                #pragma unroll
                for (int k0 = 0; k0 < 16; k0++) {
                    if (k0 & bit) continue;
                    int k1 = k0 | bit;
                    float2 a = col[k0], b = col[k1];
                    col[k0] = make_float2(m00.x*a.x - m00.y*a.y + m01.x*b.x - m01.y*b.y,
                                          m00.x*a.y + m00.y*a.x + m01.x*b.y + m01.y*b.x);
                    col[k1] = make_float2(m10.x*a.x - m10.y*a.y + m11.x*b.x - m11.y*b.y,
                                          m10.x*a.y + m10.y*a.x + m11.x*b.y + m11.y*b.x);
                }
            }
            int r = (l % (NQ - 1)) + 1;
            #pragma unroll
            for (int w = 0; w < NQ; w++) {
                int cb = 1 << (3 - w);
                int tb = 1 << (3 - ((w + r) & 3));
                #pragma unroll
                for (int k = 0; k < 16; k++) {
                    if ((k & cb) && !(k & tb)) {
                        float2 t = col[k]; col[k] = col[k | tb]; col[k | tb] = t;
                    }
                }
            }
        }
        #pragma unroll
        for (int k = 0; k < 16; k++) sU[k][c] = col[k];
    }
    __syncthreads();

    for (int pp = tid; pp < NPAIR; pp += 128) {
        int a = 0, rem = pp;
        while (rem >= 16 - a) { rem -= 16 - a; a++; }
        int b = a + rem;

        float s[4] = {0.f, 0.f, 0.f, 0.f};
        #pragma unroll
        for (int k = 0; k < 16; k++) {
            float2 ua = sU[k][a], ub = sU[k][b];
            float re = ua.x*ub.x + ua.y*ub.y;
            #pragma unroll
            for (int i = 0; i < 4; i++)
                s[i] += ((k >> (3 - i)) & 1) ? -re : re;
        }
        float scale = (a == b) ? 1.f : 2.f;
        ulonglong2 q0, q1;
        q0.x = pack2(s[0]*scale, s[0]*scale); q0.y = pack2(s[1]*scale, s[1]*scale);
        q1.x = pack2(s[2]*scale, s[2]*scale); q1.y = pack2(s[3]*scale, s[3]*scale);
        sM[pp*2 + 0] = q0;
        sM[pp*2 + 1] = q1;
    }
    __syncthreads();

    #pragma unroll 1
    for (int it = 0; it < ENC_ITERS; it++) {
        int u = (ebid * ENC_ITERS + it) * 128 + tid;   // 4-channel unit, < 64512

        // zero the 4 pad rows of encT (rows 252..255 = 8192 ull)
        if (u < 8192)
            ((ull*)(d_encT + (size_t)FAN_IN * NCH))[u] = 0ULL;

        int h = u & 1023;                  // 4-channel group within patch
        int j = u >> 10;                   // patch
        int n0 = h << 2;                   // channels n0..n0+3
        int b  = n0 >> 7;
        int m  = n0 & 127;

        const ulonglong2* xp = (const ulonglong2*)(x + (size_t)b * (SEQ_LEN*CHANS)
                                                     + (size_t)(j*STRIDE) * CHANS + m);
        const ull EPS2 = 0x358637bd358637bdULL;   // (1e-6f, 1e-6f)

        ull v0[16], v1[16];
        #pragma unroll
        for (int k = 0; k < 16; k++) {
            ulonglong2 X = __ldg(xp + k * (CHANS/4));
            v0[k] = add2(X.x, EPS2);
            v1[k] = add2(X.y, EPS2);
        }

        ull z0[4] = {0,0,0,0}, z1[4] = {0,0,0,0};
        ull nrm0 = 0ULL, nrm1 = 0ULL;
        int p = 0;
        #pragma unroll
        for (int a = 0; a < 16; a++) {
            #pragma unroll
            for (int bb = a; bb < 16; bb++) {
                ull u0 = mul2(v0[a], v0[bb]);
                ull u1 = mul2(v1[a], v1[bb]);
                if (bb == a) { nrm0 = add2(nrm0, u0); nrm1 = add2(nrm1, u1); }
                ulonglong2 q0 = sM[2*p + 0];
                ulonglong2 q1 = sM[2*p + 1];
                z0[0] = fma2(u0, q0.x, z0[0]);  z1[0] = fma2(u1, q0.x, z1[0]);
                z0[1] = fma2(u0, q0.y, z0[1]);  z1[1] = fma2(u1, q0.y, z1[1]);
                z0[2] = fma2(u0, q1.x, z0[2]);  z1[2] = fma2(u1, q1.x, z1[2]);
                z0[3] = fma2(u0, q1.y, z0[3]);  z1[3] = fma2(u1, q1.y, z1[3]);
                p++;
            }
        }
        ull inv0 = pack2(1.0f / lo2(nrm0), 1.0f / hi2(nrm0));
        ull inv1 = pack2(1.0f / lo2(nrm1), 1.0f / hi2(nrm1));

        #pragma unroll
        for (int i = 0; i < 4; i++) {
            ulonglong2 o;
            o.x = mul2(z0[i], inv0);
            o.y = mul2(z1[i], inv1);
            *(ulonglong2*)(d_encT + (size_t)(j*4 + i) * NCH + n0) = o;
        }
    }
}

// ---------------------------------------------------------------------------
// Kernel B: head-GEMM over encT (full padded 256 k), added into out with
// plain read-add-write (exclusive owner per element; ordered by launch).
// UNCHANGED from round 16.
// ---------------------------------------------------------------------------
__global__ __launch_bounds__(256, 4) void head_final(
    const float* __restrict__ head_w,
    float* __restrict__ out)
{
    __shared__ ull sS[64 * 65];            // 33.3KB: stage (2048) / reduce (4160)

    int tid = threadIdx.x;                 // 0..255
    int o0  = blockIdx.x * 8;
    int b   = blockIdx.y;

    #pragma unroll
    for (int it = 0; it < 8; it++) {
        int idx = it * 256 + tid;          // < 2048
        int r  = idx >> 8;
        int kk = idx & 255;
        float w = (kk < FAN_IN) ? head_w[(o0 + r) * FAN_IN + kk] : 0.f;
        sS[kk * 8 + r] = pack2(w, w);
    }
    __syncthreads();

    int cpg = tid & 31;                    // 4 channels: 4cpg..4cpg+3
    int g   = tid >> 5;                    // 0..7, 32 k each = 4 chunks of 8

    ull acc[2][8];
    #pragma unroll
    for (int s = 0; s < 2; s++)
        #pragma unroll
        for (int r = 0; r < 8; r++) acc[s][r] = 0ULL;

    const ulonglong2* ep = (const ulonglong2*)d_encT
        + (size_t)(g * 32) * (NCH/4) + b * (CHANS/4) + cpg;
    gemm_seg8<NCH/4>(ep, 4, (const ulonglong2*)sS + (g * 32) * 4, acc);

    __syncthreads();
    #pragma unroll
    for (int s = 0; s < 2; s++) {
        int cp = 2 * cpg + s;              // 0..63
        #pragma unroll
        for (int r = 0; r < 8; r++)
            sS[cp * 65 + g * 8 + r] = acc[s][r];
    }
    __syncthreads();

    int cp = tid & 63;
    int q  = tid >> 6;                     // 0..3
    #pragma unroll
    for (int t = 0; t < 2; t++) {
        int oo = 2 * q + t;
        ull s = 0ULL;
        #pragma unroll
        for (int gg = 0; gg < 8; gg++)
            s = add2(s, sS[cp * 65 + gg * 8 + oo]);
        ull* op = (ull*)out + ((size_t)b * PRED_LEN + o0 + oo) * (CHANS/2) + cp;
        *op = add2(*op, s);                // exclusive owner; ordered by launch
    }
}

// ---------------------------------------------------------------------------
extern "C" void kernel_launch(void* const* d_in, const int* in_sizes, int n_in,
                              void* d_out, int out_size) {
    const float* x       = (const float*)d_in[0];
    const float* weights = (const float*)d_in[1];
    const float* head_w  = (const float*)d_in[2];
    const float* head_b  = (const float*)d_in[3];
    const float* skip_w  = (const float*)d_in[4];
    const float* skip_b  = (const float*)d_in[5];
    float* out = (float*)d_out;

    fused_enc_skip<<<SKIP_BLOCKS + ENC_BLOCKS, 128>>>(x, weights, skip_w,
                                                      head_b, skip_b, out);
    head_final<<<dim3(12, BATCH), 256>>>(head_w, out);
}